// round 1
// baseline (speedup 1.0000x reference)
#include <cuda_runtime.h>
#include <math.h>
#include <float.h>

#define BD 2
#define TT 2048
#define DDIM 2048
#define NH 16
#define HD 128
#define BH (BD*NH)         // 32
#define MROWS (BD*TT)      // 4096
#define E3 (3*DDIM)        // 6144
#define SCALE 0.08838834764831843f   // 1/sqrt(128)

// ------------------ scratch (static device, allocation-free) ------------------
__device__ float g_q[(size_t)BH*TT*HD];       // 33.5 MB
__device__ float g_k[(size_t)BH*TT*HD];
__device__ float g_v[(size_t)BH*TT*HD];
__device__ float g_s[134217728ull];           // [BH][T][T] scores/probs, 512 MB
__device__ float g_attn[(size_t)MROWS*DDIM];  // 33.5 MB

// ======================= QKV GEMM: C = X * Wqkv^T + b, scatter to q/k/v =======================
// X: [4096,2048] row-major, Wqkv: [6144,2048] row-major. 128x128x8 tile, 8x8 microtile.
__global__ __launch_bounds__(256) void k_qkv_gemm(const float* __restrict__ X,
                                                  const float* __restrict__ W,
                                                  const float* __restrict__ bias)
{
    __shared__ float As[8][128];
    __shared__ float Bs[8][128];
    const int tid = threadIdx.x;
    const int tx = tid & 15, ty = tid >> 4;
    const int m0 = blockIdx.y * 128, n0 = blockIdx.x * 128;
    const int lr = tid >> 1;
    const int lc = (tid & 1) * 4;
    const float* Ap = X + (size_t)(m0 + lr) * DDIM + lc;
    const float* Bp = W + (size_t)(n0 + lr) * DDIM + lc;

    float acc[8][8];
    #pragma unroll
    for (int i = 0; i < 8; i++)
        #pragma unroll
        for (int j = 0; j < 8; j++) acc[i][j] = 0.f;

    for (int k0 = 0; k0 < DDIM; k0 += 8) {
        float4 av = *(const float4*)(Ap + k0);
        float4 bv = *(const float4*)(Bp + k0);
        __syncthreads();
        As[lc+0][lr]=av.x; As[lc+1][lr]=av.y; As[lc+2][lr]=av.z; As[lc+3][lr]=av.w;
        Bs[lc+0][lr]=bv.x; Bs[lc+1][lr]=bv.y; Bs[lc+2][lr]=bv.z; Bs[lc+3][lr]=bv.w;
        __syncthreads();
        #pragma unroll
        for (int kk = 0; kk < 8; kk++) {
            float a[8], b[8];
            *(float4*)(a)   = *(const float4*)&As[kk][ty*8];
            *(float4*)(a+4) = *(const float4*)&As[kk][ty*8+4];
            *(float4*)(b)   = *(const float4*)&Bs[kk][tx*8];
            *(float4*)(b+4) = *(const float4*)&Bs[kk][tx*8+4];
            #pragma unroll
            for (int i = 0; i < 8; i++)
                #pragma unroll
                for (int j = 0; j < 8; j++)
                    acc[i][j] = fmaf(a[i], b[j], acc[i][j]);
        }
    }
    // scatter epilogue: col group of 8 lies inside one (s, head)
    const int nb  = n0 + tx * 8;
    const int s   = nb / DDIM;
    const int rem = nb % DDIM;
    const int h   = rem >> 7;
    const int dd0 = rem & 127;
    float* dstbuf = (s == 0) ? g_q : (s == 1) ? g_k : g_v;
    float bsv[8];
    #pragma unroll
    for (int j = 0; j < 8; j++) bsv[j] = bias[nb + j];
    #pragma unroll
    for (int i = 0; i < 8; i++) {
        int m = m0 + ty * 8 + i;
        int b = m >> 11, t = m & 2047;
        float* dst = dstbuf + (((size_t)(b * NH + h) * TT + t) * HD + dd0);
        float4 o0 = make_float4(acc[i][0]+bsv[0], acc[i][1]+bsv[1], acc[i][2]+bsv[2], acc[i][3]+bsv[3]);
        float4 o1 = make_float4(acc[i][4]+bsv[4], acc[i][5]+bsv[5], acc[i][6]+bsv[6], acc[i][7]+bsv[7]);
        *(float4*)dst       = o0;
        *(float4*)(dst + 4) = o1;
    }
}

// ======================= RoPE in-place on q or k =======================
__global__ void k_rope(int which, const float* __restrict__ cs, const float* __restrict__ sn)
{
    int idx = blockIdx.x * blockDim.x + threadIdx.x;
    if (idx >= BH * TT * 64) return;
    int p  = idx & 63;
    int t  = (idx >> 6) & 2047;
    int bh = idx >> 17;                 // /(64*2048)
    float* buf = which ? g_k : g_q;
    float* ptr = buf + ((size_t)bh * TT + t) * HD;
    float c0 = cs[t*HD + p],      s0 = sn[t*HD + p];
    float c1 = cs[t*HD + p + 64], s1 = sn[t*HD + p + 64];
    float x1 = ptr[p], x2 = ptr[p + 64];
    ptr[p]      = x1 * c0 - x2 * s0;
    ptr[p + 64] = x2 * c1 + x1 * s1;
}

// ======================= Scores: S = scale * Q K^T, lower tiles only =======================
__global__ __launch_bounds__(256) void k_scores()
{
    if (blockIdx.x > blockIdx.y) return;   // causal tile skip
    const int bh = blockIdx.z;
    const float* A  = g_q + (size_t)bh * TT * HD;
    const float* Bm = g_k + (size_t)bh * TT * HD;
    float* C = g_s + (size_t)bh * TT * TT;

    __shared__ float As[8][128];
    __shared__ float Bs[8][128];
    const int tid = threadIdx.x;
    const int tx = tid & 15, ty = tid >> 4;
    const int m0 = blockIdx.y * 128, n0 = blockIdx.x * 128;
    const int lr = tid >> 1;
    const int lc = (tid & 1) * 4;
    const float* Ap = A  + (size_t)(m0 + lr) * HD + lc;
    const float* Bp = Bm + (size_t)(n0 + lr) * HD + lc;

    float acc[8][8];
    #pragma unroll
    for (int i = 0; i < 8; i++)
        #pragma unroll
        for (int j = 0; j < 8; j++) acc[i][j] = 0.f;

    for (int k0 = 0; k0 < HD; k0 += 8) {
        float4 av = *(const float4*)(Ap + k0);
        float4 bv = *(const float4*)(Bp + k0);
        __syncthreads();
        As[lc+0][lr]=av.x; As[lc+1][lr]=av.y; As[lc+2][lr]=av.z; As[lc+3][lr]=av.w;
        Bs[lc+0][lr]=bv.x; Bs[lc+1][lr]=bv.y; Bs[lc+2][lr]=bv.z; Bs[lc+3][lr]=bv.w;
        __syncthreads();
        #pragma unroll
        for (int kk = 0; kk < 8; kk++) {
            float a[8], b[8];
            *(float4*)(a)   = *(const float4*)&As[kk][ty*8];
            *(float4*)(a+4) = *(const float4*)&As[kk][ty*8+4];
            *(float4*)(b)   = *(const float4*)&Bs[kk][tx*8];
            *(float4*)(b+4) = *(const float4*)&Bs[kk][tx*8+4];
            #pragma unroll
            for (int i = 0; i < 8; i++)
                #pragma unroll
                for (int j = 0; j < 8; j++)
                    acc[i][j] = fmaf(a[i], b[j], acc[i][j]);
        }
    }
    #pragma unroll
    for (int i = 0; i < 8; i++) {
        float* dst = C + (size_t)(m0 + ty*8 + i) * TT + n0 + tx*8;
        float4 o0 = make_float4(acc[i][0]*SCALE, acc[i][1]*SCALE, acc[i][2]*SCALE, acc[i][3]*SCALE);
        float4 o1 = make_float4(acc[i][4]*SCALE, acc[i][5]*SCALE, acc[i][6]*SCALE, acc[i][7]*SCALE);
        *(float4*)dst       = o0;
        *(float4*)(dst + 4) = o1;
    }
}

// ======================= Row softmax over causal length, zero-pad to tile =======================
__global__ __launch_bounds__(256) void k_softmax()
{
    __shared__ float red[32];
    const int r = blockIdx.x;            // 0..65535
    const int i = r & 2047;
    float* row = g_s + (size_t)r * TT;
    const int L  = i + 1;
    const int Lp = ((i >> 7) + 1) << 7;  // pad to next 128 boundary
    const int tid = threadIdx.x;

    float v[8];
    float vmax = -FLT_MAX;
    #pragma unroll
    for (int it = 0; it < 8; it++) {
        int j = tid + (it << 8);
        v[it] = (j < L) ? row[j] : -FLT_MAX;
        vmax = fmaxf(vmax, v[it]);
    }
    #pragma unroll
    for (int o = 16; o; o >>= 1) vmax = fmaxf(vmax, __shfl_xor_sync(0xffffffffu, vmax, o));
    if ((tid & 31) == 0) red[tid >> 5] = vmax;
    __syncthreads();
    if (tid < 32) {
        float t2 = (tid < 8) ? red[tid] : -FLT_MAX;
        #pragma unroll
        for (int o = 4; o; o >>= 1) t2 = fmaxf(t2, __shfl_xor_sync(0xffffffffu, t2, o));
        if (tid == 0) red[0] = t2;
    }
    __syncthreads();
    vmax = red[0];
    __syncthreads();

    float sum = 0.f;
    #pragma unroll
    for (int it = 0; it < 8; it++) {
        float e = __expf(v[it] - vmax);  // exp(-inf) -> 0 for padding lanes
        v[it] = e;
        sum += e;
    }
    #pragma unroll
    for (int o = 16; o; o >>= 1) sum += __shfl_xor_sync(0xffffffffu, sum, o);
    if ((tid & 31) == 0) red[tid >> 5] = sum;
    __syncthreads();
    if (tid < 32) {
        float t2 = (tid < 8) ? red[tid] : 0.f;
        #pragma unroll
        for (int o = 4; o; o >>= 1) t2 += __shfl_xor_sync(0xffffffffu, t2, o);
        if (tid == 0) red[0] = t2;
    }
    __syncthreads();
    const float inv = 1.0f / red[0];
    #pragma unroll
    for (int it = 0; it < 8; it++) {
        int j = tid + (it << 8);
        if (j < Lp) row[j] = v[it] * inv;   // v[it]==0 beyond L -> zero pad
    }
}

// ======================= PV GEMM (NN): O = P * V, causal K-limit, write [b,t,h,d] =======================
__global__ __launch_bounds__(256) void k_pv()
{
    const int bh = blockIdx.z;
    const int m0 = blockIdx.y * 128;
    const int Klim = m0 + 128;
    const float* A  = g_s + (size_t)bh * TT * TT;   // P row-major [T,T]
    const float* Bm = g_v + (size_t)bh * TT * HD;   // V row-major [T,128]

    __shared__ float As[8][128];
    __shared__ float Bs[8][128];
    const int tid = threadIdx.x;
    const int tx = tid & 15, ty = tid >> 4;
    const int lra = tid >> 1,  lca = (tid & 1) * 4;   // A tile loads (transpose)
    const int lrb = tid >> 5,  lcb = (tid & 31) * 4;  // B tile loads (direct)

    float acc[8][8];
    #pragma unroll
    for (int i = 0; i < 8; i++)
        #pragma unroll
        for (int j = 0; j < 8; j++) acc[i][j] = 0.f;

    for (int k0 = 0; k0 < Klim; k0 += 8) {
        float4 av = *(const float4*)(A  + (size_t)(m0 + lra) * TT + k0 + lca);
        float4 bv = *(const float4*)(Bm + (size_t)(k0 + lrb) * HD + lcb);
        __syncthreads();
        As[lca+0][lra]=av.x; As[lca+1][lra]=av.y; As[lca+2][lra]=av.z; As[lca+3][lra]=av.w;
        *(float4*)&Bs[lrb][lcb] = bv;
        __syncthreads();
        #pragma unroll
        for (int kk = 0; kk < 8; kk++) {
            float a[8], b[8];
            *(float4*)(a)   = *(const float4*)&As[kk][ty*8];
            *(float4*)(a+4) = *(const float4*)&As[kk][ty*8+4];
            *(float4*)(b)   = *(const float4*)&Bs[kk][tx*8];
            *(float4*)(b+4) = *(const float4*)&Bs[kk][tx*8+4];
            #pragma unroll
            for (int i = 0; i < 8; i++)
                #pragma unroll
                for (int j = 0; j < 8; j++)
                    acc[i][j] = fmaf(a[i], b[j], acc[i][j]);
        }
    }
    const int b = bh >> 4, h = bh & 15;
    #pragma unroll
    for (int i = 0; i < 8; i++) {
        int t = m0 + ty * 8 + i;
        float* dst = g_attn + ((size_t)(b * TT + t) * DDIM + h * HD + tx * 8);
        *(float4*)dst       = make_float4(acc[i][0], acc[i][1], acc[i][2], acc[i][3]);
        *(float4*)(dst + 4) = make_float4(acc[i][4], acc[i][5], acc[i][6], acc[i][7]);
    }
}

// ======================= Output GEMM: out = attn * Wout^T + b =======================
__global__ __launch_bounds__(256) void k_out(const float* __restrict__ W,
                                             const float* __restrict__ bias,
                                             float* __restrict__ Cout)
{
    __shared__ float As[8][128];
    __shared__ float Bs[8][128];
    const int tid = threadIdx.x;
    const int tx = tid & 15, ty = tid >> 4;
    const int m0 = blockIdx.y * 128, n0 = blockIdx.x * 128;
    const int lr = tid >> 1;
    const int lc = (tid & 1) * 4;
    const float* Ap = g_attn + (size_t)(m0 + lr) * DDIM + lc;
    const float* Bp = W      + (size_t)(n0 + lr) * DDIM + lc;

    float acc[8][8];
    #pragma unroll
    for (int i = 0; i < 8; i++)
        #pragma unroll
        for (int j = 0; j < 8; j++) acc[i][j] = 0.f;

    for (int k0 = 0; k0 < DDIM; k0 += 8) {
        float4 av = *(const float4*)(Ap + k0);
        float4 bv = *(const float4*)(Bp + k0);
        __syncthreads();
        As[lc+0][lr]=av.x; As[lc+1][lr]=av.y; As[lc+2][lr]=av.z; As[lc+3][lr]=av.w;
        Bs[lc+0][lr]=bv.x; Bs[lc+1][lr]=bv.y; Bs[lc+2][lr]=bv.z; Bs[lc+3][lr]=bv.w;
        __syncthreads();
        #pragma unroll
        for (int kk = 0; kk < 8; kk++) {
            float a[8], b[8];
            *(float4*)(a)   = *(const float4*)&As[kk][ty*8];
            *(float4*)(a+4) = *(const float4*)&As[kk][ty*8+4];
            *(float4*)(b)   = *(const float4*)&Bs[kk][tx*8];
            *(float4*)(b+4) = *(const float4*)&Bs[kk][tx*8+4];
            #pragma unroll
            for (int i = 0; i < 8; i++)
                #pragma unroll
                for (int j = 0; j < 8; j++)
                    acc[i][j] = fmaf(a[i], b[j], acc[i][j]);
        }
    }
    #pragma unroll
    for (int i = 0; i < 8; i++) {
        int m = m0 + ty * 8 + i;
        int n = n0 + tx * 8;
        float* dst = Cout + (size_t)m * DDIM + n;
        *(float4*)dst       = make_float4(acc[i][0]+bias[n+0], acc[i][1]+bias[n+1],
                                          acc[i][2]+bias[n+2], acc[i][3]+bias[n+3]);
        *(float4*)(dst + 4) = make_float4(acc[i][4]+bias[n+4], acc[i][5]+bias[n+5],
                                          acc[i][6]+bias[n+6], acc[i][7]+bias[n+7]);
    }
}

// ======================= launch =======================
extern "C" void kernel_launch(void* const* d_in, const int* in_sizes, int n_in,
                              void* d_out, int out_size)
{
    (void)in_sizes; (void)n_in; (void)out_size;
    const float* x      = (const float*)d_in[0];
    const float* rc     = (const float*)d_in[1];
    const float* rs     = (const float*)d_in[2];
    const float* qkv_w  = (const float*)d_in[3];
    const float* qkv_b  = (const float*)d_in[4];
    const float* out_w  = (const float*)d_in[5];
    const float* out_b  = (const float*)d_in[6];
    float* out = (float*)d_out;

    k_qkv_gemm<<<dim3(E3/128, MROWS/128), 256>>>(x, qkv_w, qkv_b);
    int rope_n = BH * TT * 64;
    k_rope<<<(rope_n + 255) / 256, 256>>>(0, rc, rs);
    k_rope<<<(rope_n + 255) / 256, 256>>>(1, rc, rs);
    k_scores<<<dim3(TT/128, TT/128, BH), 256>>>();
    k_softmax<<<BH * TT, 256>>>();
    k_pv<<<dim3(1, TT/128, BH), 256>>>();
    k_out<<<dim3(DDIM/128, MROWS/128), 256>>>(out_w, out_b, out);
}

// round 6
// speedup vs baseline: 1.8622x; 1.8622x over previous
#include <cuda_runtime.h>
#include <cstdint>
#include <math.h>
#include <float.h>

#define BD 2
#define TT 2048
#define DDIM 2048
#define NH 16
#define HD 128
#define BH (BD*NH)         // 32
#define MROWS (BD*TT)      // 4096
#define E3 (3*DDIM)        // 6144
#define SCALE 0.08838834764831843f

#define BUFSZ 33280        // A 16384 + B 16896 (64 blocks * 264B)
#define SMEM_MAIN (2*BUFSZ)        // 66560
#define SMEM_QKV  (128*132*4)      // 67584 (union with mainloop buffers)

// ------------------ scratch (static device, allocation-free) ------------------
__device__ float g_q[(size_t)BH*TT*HD];
__device__ float g_k[(size_t)BH*TT*HD];
__device__ float g_vt[(size_t)BH*HD*TT];      // V transposed: [bh][d][t]
__device__ float g_s[(size_t)BH*TT*TT];       // scores/probs 512MB
__device__ float g_attn[(size_t)MROWS*DDIM];

// ------------------ helpers ------------------
static __device__ __forceinline__ uint32_t f2tf32(float x){
    uint32_t y; asm("cvt.rn.tf32.f32 %0, %1;" : "=r"(y) : "f"(x)); return y;
}

static __device__ __forceinline__ void mma8(float* c, const uint4& a, const uint2& b){
    asm volatile(
        "mma.sync.aligned.m16n8k8.row.col.f32.tf32.tf32.f32 "
        "{%0,%1,%2,%3}, {%4,%5,%6,%7}, {%8,%9}, {%0,%1,%2,%3};"
        : "+f"(c[0]), "+f"(c[1]), "+f"(c[2]), "+f"(c[3])
        : "r"(a.x), "r"(a.y), "r"(a.z), "r"(a.w), "r"(b.x), "r"(b.y));
}

// Store one float4 of A-source and one of B-source into fragment-order smem.
// A unit (16B) = lane's {a0,a1,a2,a3}; B unit (8B) = lane's {b0,b1}.
static __device__ __forceinline__ void stage_store(char* buf, const float4& va, const float4& vb,
                                                   int r, int cc)
{
    float av[4] = {va.x, va.y, va.z, va.w};
    float bv[4] = {vb.x, vb.y, vb.z, vb.w};
    const int mi2 = r >> 4, gA = r & 7, hi = (r >> 3) & 1;
    const int ntB = r >> 3, gB = r & 7;
    #pragma unroll
    for (int dt = 0; dt < 4; dt++){
        const int k = cc*4 + dt;
        const int ks = k >> 3, t = k & 3, thi = (k >> 2) & 1;
        const int sa = 4*gA + ((t + (gA >> 1)) & 3);
        *(uint32_t*)(buf + (((mi2*4 + ks) << 9) + sa*16 + (hi + 2*thi)*4)) = f2tf32(av[dt]);
        const int sb = 4*gB + ((t + (gB >> 1)) & 3);
        *(uint32_t*)(buf + (16384 + (ntB*4 + ks)*264 + sb*8 + thi*4)) = f2tf32(bv[dt]);
    }
}

static __device__ __forceinline__ void compute_chunk(const char* buf, float (&acc)[4][4][4],
                                                     int wm, int wn, int l)
{
    const int sig = 4*(l >> 2) + (((l & 3) + (l >> 3)) & 3);
    const int sa16 = sig * 16;
    const int sb8  = sig * 8;
    #pragma unroll
    for (int ks = 0; ks < 4; ks++){
        uint4 a[4]; uint2 b[4];
        #pragma unroll
        for (int mi = 0; mi < 4; mi++)
            a[mi] = *(const uint4*)(buf + ((((wm*4 + mi)*4 + ks) << 9) + sa16));
        #pragma unroll
        for (int ni = 0; ni < 4; ni++)
            b[ni] = *(const uint2*)(buf + (16384 + ((wn*4 + ni)*4 + ks)*264 + sb8));
        #pragma unroll
        for (int mi = 0; mi < 4; mi++)
            #pragma unroll
            for (int ni = 0; ni < 4; ni++)
                mma8(acc[mi][ni], a[mi], b[ni]);
    }
}

// C[128,128] += A[128,K] * B[128,K]^T (both K-major row-major sources), K = nIter*32.
static __device__ __forceinline__ void gemm_loop(char* sm, float (&acc)[4][4][4],
    const float* __restrict__ A, size_t lda,
    const float* __restrict__ B, size_t ldb, int nIter)
{
    const int tid = threadIdx.x;
    const int r = tid & 127, ccb = (tid >> 7) * 4;
    const int w = tid >> 5, wm = w >> 2, wn = w & 3, l = tid & 31;

    const float* Ar = A + (size_t)r * lda;
    const float* Br = B + (size_t)r * ldb;

    float4 pa[4], pb[4];
    #pragma unroll
    for (int i = 0; i < 4; i++){
        pa[i] = *(const float4*)(Ar + (ccb + i)*4);
        pb[i] = *(const float4*)(Br + (ccb + i)*4);
    }
    #pragma unroll
    for (int i = 0; i < 4; i++) stage_store(sm, pa[i], pb[i], r, ccb + i);
    if (nIter > 1){
        #pragma unroll
        for (int i = 0; i < 4; i++){
            pa[i] = *(const float4*)(Ar + 32 + (ccb + i)*4);
            pb[i] = *(const float4*)(Br + 32 + (ccb + i)*4);
        }
    }
    __syncthreads();

    for (int kt = 0; kt < nIter; kt++){
        char* cur = sm + (kt & 1) * BUFSZ;
        if (kt + 1 < nIter){
            char* nxt = sm + ((kt + 1) & 1) * BUFSZ;
            #pragma unroll
            for (int i = 0; i < 4; i++) stage_store(nxt, pa[i], pb[i], r, ccb + i);
        }
        if (kt + 2 < nIter){
            const int ko = (kt + 2) * 32;
            #pragma unroll
            for (int i = 0; i < 4; i++){
                pa[i] = *(const float4*)(Ar + ko + (ccb + i)*4);
                pb[i] = *(const float4*)(Br + ko + (ccb + i)*4);
            }
        }
        compute_chunk(cur, acc, wm, wn, l);
        __syncthreads();
    }
}

#define GEMM_PROLOGUE() \
    extern __shared__ char sm[]; \
    const int tid = threadIdx.x; \
    const int w = tid >> 5, wm = w >> 2, wn = w & 3, l = tid & 31; \
    const int fg = l >> 2, ft = l & 3; \
    float acc[4][4][4]; \
    _Pragma("unroll") for (int mi = 0; mi < 4; mi++) \
    _Pragma("unroll") for (int ni = 0; ni < 4; ni++) \
    _Pragma("unroll") for (int j = 0; j < 4; j++) acc[mi][ni][j] = 0.f;

// ======================= QKV GEMM + fused bias/RoPE + V transpose =======================
__global__ __launch_bounds__(256) void k_qkv(const float* __restrict__ X,
                                             const float* __restrict__ W,
                                             const float* __restrict__ bias,
                                             const float* __restrict__ cs,
                                             const float* __restrict__ sn)
{
    GEMM_PROLOGUE();
    const int n0 = blockIdx.x * 128, m0 = blockIdx.y * 128;
    gemm_loop(sm, acc, X + (size_t)m0*DDIM, DDIM, W + (size_t)n0*DDIM, DDIM, DDIM/32);

    // stage tile (+bias) to smem [128][132]
    float* smC = (float*)sm;
    #pragma unroll
    for (int ni = 0; ni < 4; ni++){
        const int c = 32*wn + 8*ni + 2*ft;
        const float b0 = bias[n0 + c], b1 = bias[n0 + c + 1];
        #pragma unroll
        for (int mi = 0; mi < 4; mi++){
            const int rr = 64*wm + 16*mi + fg;
            smC[rr*132 + c]     = acc[mi][ni][0] + b0;
            smC[rr*132 + c + 1] = acc[mi][ni][1] + b1;
            smC[(rr+8)*132 + c]     = acc[mi][ni][2] + b0;
            smC[(rr+8)*132 + c + 1] = acc[mi][ni][3] + b1;
        }
    }
    __syncthreads();

    const int s = n0 >> 11, h = (n0 & 2047) >> 7;
    const int bb = m0 >> 11, t0 = m0 & 2047;
    if (s < 2){
        // RoPE on q/k: pairs (c, c+64)
        const int r = tid & 127, half = tid >> 7;
        const int t = t0 + r;
        float* dst = (s ? g_k : g_q) + ((size_t)(bb*NH + h)*TT + t)*HD;
        const float* csr = cs + (size_t)t*HD;
        const float* snr = sn + (size_t)t*HD;
        #pragma unroll
        for (int jj = 0; jj < 8; jj++){
            const int c = half*32 + jj*4;
            float4 x1 = *(const float4*)(smC + r*132 + c);
            float4 x2 = *(const float4*)(smC + r*132 + c + 64);
            float4 c0 = *(const float4*)(csr + c);
            float4 s0 = *(const float4*)(snr + c);
            float4 c1 = *(const float4*)(csr + c + 64);
            float4 s1 = *(const float4*)(snr + c + 64);
            float4 o1 = make_float4(x1.x*c0.x - x2.x*s0.x, x1.y*c0.y - x2.y*s0.y,
                                    x1.z*c0.z - x2.z*s0.z, x1.w*c0.w - x2.w*s0.w);
            float4 o2 = make_float4(x2.x*c1.x + x1.x*s1.x, x2.y*c1.y + x1.y*s1.y,
                                    x2.z*c1.z + x1.z*s1.z, x2.w*c1.w + x1.w*s1.w);
            *(float4*)(dst + c)      = o1;
            *(float4*)(dst + c + 64) = o2;
        }
    } else {
        // V: write transposed [d][t]
        float* dstb = g_vt + (size_t)(bb*NH + h)*HD*TT;
        #pragma unroll
        for (int i = 0; i < 16; i++){
            const int ii = tid + i*256;
            const int d = ii >> 5, tq = ii & 31;
            float4 v;
            v.x = smC[(tq*4 + 0)*132 + d];
            v.y = smC[(tq*4 + 1)*132 + d];
            v.z = smC[(tq*4 + 2)*132 + d];
            v.w = smC[(tq*4 + 3)*132 + d];
            *(float4*)(dstb + (size_t)d*TT + t0 + tq*4) = v;
        }
    }
}

// ======================= Scores: S = scale * Q K^T, lower tiles only =======================
__global__ __launch_bounds__(256) void k_scores()
{
    if (blockIdx.x > blockIdx.y) return;
    GEMM_PROLOGUE();
    const int bh = blockIdx.z;
    const int m0 = blockIdx.y * 128, n0 = blockIdx.x * 128;
    gemm_loop(sm, acc,
              g_q + (size_t)bh*TT*HD + (size_t)m0*HD, HD,
              g_k + (size_t)bh*TT*HD + (size_t)n0*HD, HD, HD/32);
    float* C = g_s + (size_t)bh*TT*TT;
    #pragma unroll
    for (int mi = 0; mi < 4; mi++){
        const int rl = m0 + 64*wm + 16*mi + fg;
        #pragma unroll
        for (int ni = 0; ni < 4; ni++){
            const int c = n0 + 32*wn + 8*ni + 2*ft;
            *(float2*)(C + (size_t)rl*TT + c)     = make_float2(acc[mi][ni][0]*SCALE, acc[mi][ni][1]*SCALE);
            *(float2*)(C + (size_t)(rl+8)*TT + c) = make_float2(acc[mi][ni][2]*SCALE, acc[mi][ni][3]*SCALE);
        }
    }
}

// ======================= Row softmax, zero-pad to tile boundary =======================
__global__ __launch_bounds__(256) void k_softmax()
{
    __shared__ float red[32];
    const int r = blockIdx.x;
    const int i = r & 2047;
    float* row = g_s + (size_t)r * TT;
    const int L  = i + 1;
    const int Lp = ((i >> 7) + 1) << 7;
    const int tid = threadIdx.x;

    float v[8];
    float vmax = -FLT_MAX;
    #pragma unroll
    for (int it = 0; it < 8; it++){
        int j = tid + (it << 8);
        v[it] = (j < L) ? row[j] : -FLT_MAX;
        vmax = fmaxf(vmax, v[it]);
    }
    #pragma unroll
    for (int o = 16; o; o >>= 1) vmax = fmaxf(vmax, __shfl_xor_sync(0xffffffffu, vmax, o));
    if ((tid & 31) == 0) red[tid >> 5] = vmax;
    __syncthreads();
    if (tid < 32){
        float t2 = (tid < 8) ? red[tid] : -FLT_MAX;
        #pragma unroll
        for (int o = 4; o; o >>= 1) t2 = fmaxf(t2, __shfl_xor_sync(0xffffffffu, t2, o));
        if (tid == 0) red[0] = t2;
    }
    __syncthreads();
    vmax = red[0];
    __syncthreads();

    float sum = 0.f;
    #pragma unroll
    for (int it = 0; it < 8; it++){
        float e = __expf(v[it] - vmax);
        v[it] = e;
        sum += e;
    }
    #pragma unroll
    for (int o = 16; o; o >>= 1) sum += __shfl_xor_sync(0xffffffffu, sum, o);
    if ((tid & 31) == 0) red[tid >> 5] = sum;
    __syncthreads();
    if (tid < 32){
        float t2 = (tid < 8) ? red[tid] : 0.f;
        #pragma unroll
        for (int o = 4; o; o >>= 1) t2 += __shfl_xor_sync(0xffffffffu, t2, o);
        if (tid == 0) red[0] = t2;
    }
    __syncthreads();
    const float inv = 1.0f / red[0];
    #pragma unroll
    for (int it = 0; it < 8; it++){
        int j = tid + (it << 8);
        if (j < Lp) row[j] = v[it] * inv;
    }
}

// ======================= PV: O = P * V (V^T K-major), causal K-limit =======================
__global__ __launch_bounds__(256) void k_pv()
{
    GEMM_PROLOGUE();
    const int mt = blockIdx.x, bh = blockIdx.y;
    const int m0 = mt * 128;
    gemm_loop(sm, acc,
              g_s  + (size_t)bh*TT*TT + (size_t)m0*TT, TT,
              g_vt + (size_t)bh*HD*TT, TT, (mt + 1) * 4);
    const int bb = bh >> 4, h = bh & 15;
    #pragma unroll
    for (int mi = 0; mi < 4; mi++){
        const int m = m0 + 64*wm + 16*mi + fg;
        float* d0 = g_attn + ((size_t)(bb*TT + m))*DDIM + h*HD;
        float* d1 = g_attn + ((size_t)(bb*TT + m + 8))*DDIM + h*HD;
        #pragma unroll
        for (int ni = 0; ni < 4; ni++){
            const int c = 32*wn + 8*ni + 2*ft;
            *(float2*)(d0 + c) = make_float2(acc[mi][ni][0], acc[mi][ni][1]);
            *(float2*)(d1 + c) = make_float2(acc[mi][ni][2], acc[mi][ni][3]);
        }
    }
}

// ======================= Output projection =======================
__global__ __launch_bounds__(256) void k_out(const float* __restrict__ W,
                                             const float* __restrict__ bias,
                                             float* __restrict__ Cout)
{
    GEMM_PROLOGUE();
    const int n0 = blockIdx.x * 128, m0 = blockIdx.y * 128;
    gemm_loop(sm, acc, g_attn + (size_t)m0*DDIM, DDIM, W + (size_t)n0*DDIM, DDIM, DDIM/32);
    #pragma unroll
    for (int ni = 0; ni < 4; ni++){
        const int c = n0 + 32*wn + 8*ni + 2*ft;
        const float b0 = bias[c], b1 = bias[c + 1];
        #pragma unroll
        for (int mi = 0; mi < 4; mi++){
            const int m = m0 + 64*wm + 16*mi + fg;
            *(float2*)(Cout + (size_t)m*DDIM + c)     = make_float2(acc[mi][ni][0] + b0, acc[mi][ni][1] + b1);
            *(float2*)(Cout + (size_t)(m+8)*DDIM + c) = make_float2(acc[mi][ni][2] + b0, acc[mi][ni][3] + b1);
        }
    }
}

// ======================= launch =======================
extern "C" void kernel_launch(void* const* d_in, const int* in_sizes, int n_in,
                              void* d_out, int out_size)
{
    (void)in_sizes; (void)n_in; (void)out_size;
    const float* x      = (const float*)d_in[0];
    const float* rc     = (const float*)d_in[1];
    const float* rs     = (const float*)d_in[2];
    const float* qkv_w  = (const float*)d_in[3];
    const float* qkv_b  = (const float*)d_in[4];
    const float* out_w  = (const float*)d_in[5];
    const float* out_b  = (const float*)d_in[6];
    float* out = (float*)d_out;

    cudaFuncSetAttribute(k_qkv,    cudaFuncAttributeMaxDynamicSharedMemorySize, SMEM_QKV);
    cudaFuncSetAttribute(k_scores, cudaFuncAttributeMaxDynamicSharedMemorySize, SMEM_MAIN);
    cudaFuncSetAttribute(k_pv,     cudaFuncAttributeMaxDynamicSharedMemorySize, SMEM_MAIN);
    cudaFuncSetAttribute(k_out,    cudaFuncAttributeMaxDynamicSharedMemorySize, SMEM_MAIN);

    k_qkv<<<dim3(E3/128, MROWS/128), 256, SMEM_QKV>>>(x, qkv_w, qkv_b, rc, rs);
    k_scores<<<dim3(TT/128, TT/128, BH), 256, SMEM_MAIN>>>();
    k_softmax<<<BH * TT, 256>>>();
    k_pv<<<dim3(TT/128, BH), 256, SMEM_MAIN>>>();
    k_out<<<dim3(DDIM/128, MROWS/128), 256, SMEM_MAIN>>>(out_w, out_b, out);
}